// round 15
// baseline (speedup 1.0000x reference)
#include <cuda_runtime.h>
#include <cuda_fp16.h>
#include <cstdint>

#define N_USERS 100000
#define N_ITEMS 60000
#define N_NODES (N_USERS + N_ITEMS)
#define EMB_DIM 128
#define VEC (EMB_DIM / 4)        // 32 chunks/row: float4 (fp32) or uint2 (fp16x4)
#define N_EDGES 1500000
#define CAP 64                   // bucket capacity per node (max deg ~28 expected)
#define MAX_SPILL 4096           // spill is statistically impossible; small list

static_assert((N_EDGES & 1) == 0, "permute int2 path requires even N_EDGES");

// Scratch (__device__ globals per allocation-free rule)
__device__ uint2 g_x0h[(size_t)N_NODES * VEC];
__device__ uint2 g_x1[(size_t)N_NODES * VEC];
__device__ uint2 g_x2[(size_t)N_NODES * VEC];
__device__ float g_invdeg[N_NODES];
__device__ int   g_count[N_NODES];
__device__ int   g_bucket[(size_t)N_NODES * CAP];   // 41 MB, 256B-aligned rows
__device__ int   g_spill_dst[MAX_SPILL];
__device__ int   g_spill_src[MAX_SPILL];
__device__ int   g_spill_count[1];

// ---------------------------------------------------------------------------
__device__ __forceinline__ __half2 h2(uint32_t b) {
    return *reinterpret_cast<__half2*>(&b);
}
__device__ __forceinline__ float4 h4_to_f4(uint2 u) {
    float2 lo = __half22float2(h2(u.x));
    float2 hi = __half22float2(h2(u.y));
    float4 r; r.x = lo.x; r.y = lo.y; r.z = hi.x; r.w = hi.y;
    return r;
}
__device__ __forceinline__ uint2 f4_to_h4(float4 v) {
    __half2 lo = __floats2half2_rn(v.x, v.y);
    __half2 hi = __floats2half2_rn(v.z, v.w);
    uint2 u;
    u.x = *reinterpret_cast<uint32_t*>(&lo);
    u.y = *reinterpret_cast<uint32_t*>(&hi);
    return u;
}

// 1) pure streaming convert: concat(ue,ie) fp32 -> fp16 table
__global__ void convert_kernel(const float4* __restrict__ ue,
                               const float4* __restrict__ ie,
                               uint2* __restrict__ x0h) {
    long i = (long)blockIdx.x * blockDim.x + threadIdx.x;
    const long total = (long)N_NODES * VEC;        // 5,120,000
    if (i >= total) return;
    const long user_lim = (long)N_USERS * VEC;
    float4 v = (i < user_lim) ? __ldcs(&ue[i]) : __ldcs(&ie[i - user_lim]);
    __stcs(&x0h[i], f4_to_h4(v));
}

// 2) direct bucket binning: no histogram/offset pass. Two edges per thread.
__global__ void permute_kernel(const int2* __restrict__ src2,
                               const int2* __restrict__ dst2,
                               int* __restrict__ count,
                               int* __restrict__ bucket,
                               int* __restrict__ spill_dst,
                               int* __restrict__ spill_src,
                               int* __restrict__ spill_count) {
    int t = blockIdx.x * blockDim.x + threadIdx.x;
    if (t >= N_EDGES / 2) return;
    int2 s = __ldg(&src2[t]);
    int2 d = __ldg(&dst2[t]);
    int p0 = atomicAdd(&count[d.x], 1);
    if (p0 < CAP) bucket[d.x * CAP + p0] = s.x;
    else {
        int sp = atomicAdd(spill_count, 1);
        if (sp < MAX_SPILL) { spill_dst[sp] = d.x; spill_src[sp] = s.x; }
    }
    int p1 = atomicAdd(&count[d.y], 1);
    if (p1 < CAP) bucket[d.y * CAP + p1] = s.y;
    else {
        int sp = atomicAdd(spill_count, 1);
        if (sp < MAX_SPILL) { spill_dst[sp] = d.y; spill_src[sp] = s.y; }
    }
}

// 3) invdeg from counts
__global__ void invdeg_kernel(const int* __restrict__ count,
                              float* __restrict__ invdeg) {
    int v = blockIdx.x * blockDim.x + threadIdx.x;
    if (v >= N_NODES) return;
    int d = count[v];
    invdeg[v] = (d > 0) ? (1.0f / (float)d) : 0.0f;
}

// ---------------------------------------------------------------------------
// Warp-per-node mean over an fp16 table. Bucket segment is 256B-aligned at
// v*CAP, so index loads are uniform int4 (2 LDG.128 per 8-edge iter).
// Depth-3 HADD2 tree, one convert per half2 chunk, fp32 accumulation.
__device__ __forceinline__ float4 row_mean_h(const int* __restrict__ count,
                                             const int* __restrict__ bucket,
                                             const float* __restrict__ invdeg,
                                             const uint2* __restrict__ xin,
                                             int w, int lane) {
    int nd = __ldg(&count[w]);
    int n = (nd < CAP) ? nd : CAP;
    const int4* b4 = reinterpret_cast<const int4*>(bucket) + w * (CAP / 4);
    float2 aLo = {0.f, 0.f}, aHi = {0.f, 0.f};
    int j = 0;
    for (; j + 8 <= n; j += 8) {
        int4 A = __ldg(&b4[j >> 2]);
        int4 B = __ldg(&b4[(j >> 2) + 1]);
        uint2 u0 = __ldg(&xin[(long)A.x * VEC + lane]);
        uint2 u1 = __ldg(&xin[(long)A.y * VEC + lane]);
        uint2 u2 = __ldg(&xin[(long)A.z * VEC + lane]);
        uint2 u3 = __ldg(&xin[(long)A.w * VEC + lane]);
        uint2 u4 = __ldg(&xin[(long)B.x * VEC + lane]);
        uint2 u5 = __ldg(&xin[(long)B.y * VEC + lane]);
        uint2 u6 = __ldg(&xin[(long)B.z * VEC + lane]);
        uint2 u7 = __ldg(&xin[(long)B.w * VEC + lane]);
        __half2 tL = __hadd2(__hadd2(__hadd2(h2(u0.x), h2(u1.x)),
                                     __hadd2(h2(u2.x), h2(u3.x))),
                             __hadd2(__hadd2(h2(u4.x), h2(u5.x)),
                                     __hadd2(h2(u6.x), h2(u7.x))));
        __half2 tH = __hadd2(__hadd2(__hadd2(h2(u0.y), h2(u1.y)),
                                     __hadd2(h2(u2.y), h2(u3.y))),
                             __hadd2(__hadd2(h2(u4.y), h2(u5.y)),
                                     __hadd2(h2(u6.y), h2(u7.y))));
        float2 f;
        f = __half22float2(tL); aLo.x += f.x; aLo.y += f.y;
        f = __half22float2(tH); aHi.x += f.x; aHi.y += f.y;
    }
    for (; j + 4 <= n; j += 4) {
        int4 A = __ldg(&b4[j >> 2]);
        uint2 u0 = __ldg(&xin[(long)A.x * VEC + lane]);
        uint2 u1 = __ldg(&xin[(long)A.y * VEC + lane]);
        uint2 u2 = __ldg(&xin[(long)A.z * VEC + lane]);
        uint2 u3 = __ldg(&xin[(long)A.w * VEC + lane]);
        __half2 tL = __hadd2(__hadd2(h2(u0.x), h2(u1.x)),
                             __hadd2(h2(u2.x), h2(u3.x)));
        __half2 tH = __hadd2(__hadd2(h2(u0.y), h2(u1.y)),
                             __hadd2(h2(u2.y), h2(u3.y)));
        float2 f;
        f = __half22float2(tL); aLo.x += f.x; aLo.y += f.y;
        f = __half22float2(tH); aHi.x += f.x; aHi.y += f.y;
    }
    const int* bs = bucket + w * CAP;
    for (; j < n; ++j) {                 // <=3 remainders in fp32
        int s = __ldg(&bs[j]);
        float4 v = h4_to_f4(__ldg(&xin[(long)s * VEC + lane]));
        aLo.x += v.x; aLo.y += v.y; aHi.x += v.z; aHi.y += v.w;
    }
    float sc = __ldg(&invdeg[w]);
    float4 r;
    r.x = aLo.x * sc; r.y = aLo.y * sc;
    r.z = aHi.x * sc; r.w = aHi.y * sc;
    return r;
}

// Layers 1 & 2: xout (fp16) = A~ @ xin (fp16)
__global__ void __launch_bounds__(256)
layer_kernel(const int* __restrict__ count, const int* __restrict__ bucket,
             const float* __restrict__ invdeg,
             const uint2* __restrict__ xin, uint2* __restrict__ xout) {
    int w = (blockIdx.x * blockDim.x + threadIdx.x) >> 5;
    int lane = threadIdx.x & 31;
    if (w >= N_NODES) return;
    float4 r = row_mean_h(count, bucket, invdeg, xin, w, lane);
    xout[(long)w * VEC + lane] = f4_to_h4(r);   // next gather table: keep in L2
}

// Spill fixup for layers 1/2: single warp walks spill edges SEQUENTIALLY
// (lane owns its chunk; read-modify-write, no atomics needed).
// Zero-trip when spill_count == 0 (the norm for this input).
__global__ void fixup_h_kernel(const int* __restrict__ spill_dst,
                               const int* __restrict__ spill_src,
                               const int* __restrict__ spill_count,
                               const float* __restrict__ invdeg,
                               const uint2* __restrict__ xin,
                               uint2* __restrict__ xout) {
    int n = *spill_count;
    if (n > MAX_SPILL) n = MAX_SPILL;
    int lane = threadIdx.x;              // blockDim.x == 32, one warp
    for (int e = 0; e < n; ++e) {
        int d = spill_dst[e], s = spill_src[e];
        float sc = invdeg[d];
        float4 v = h4_to_f4(xin[(long)s * VEC + lane]);
        long o = (long)d * VEC + lane;
        float4 cur = h4_to_f4(xout[o]);
        cur.x += sc * v.x; cur.y += sc * v.y;
        cur.z += sc * v.z; cur.w += sc * v.w;
        xout[o] = f4_to_h4(cur);
        __syncwarp();                    // order RMW across sequential edges
    }
}

// Spill fixup for layer 3: sequential single warp, fp32 RMW on out
__global__ void fixup_f_kernel(const int* __restrict__ spill_dst,
                               const int* __restrict__ spill_src,
                               const int* __restrict__ spill_count,
                               const float* __restrict__ invdeg,
                               const uint2* __restrict__ x2,
                               float4* __restrict__ out) {
    int n = *spill_count;
    if (n > MAX_SPILL) n = MAX_SPILL;
    int lane = threadIdx.x;              // one warp
    for (int e = 0; e < n; ++e) {
        int d = spill_dst[e], s = spill_src[e];
        float sc = 0.25f * invdeg[d];
        float4 v = h4_to_f4(x2[(long)s * VEC + lane]);
        long o = (long)d * VEC + lane;
        float4 cur = out[o];
        cur.x += sc * v.x; cur.y += sc * v.y;
        cur.z += sc * v.z; cur.w += sc * v.w;
        out[o] = cur;
        __syncwarp();
    }
}

// Layer 3 fused finale: r = A~ @ x2 (regs only); out = 0.25*(x0_fp32+x1+x2+r)
__global__ void __launch_bounds__(256)
layer3_kernel(const int* __restrict__ count, const int* __restrict__ bucket,
              const float* __restrict__ invdeg,
              const float4* __restrict__ ue, const float4* __restrict__ ie,
              const uint2* __restrict__ x1, const uint2* __restrict__ x2,
              float4* __restrict__ out) {
    int w = (blockIdx.x * blockDim.x + threadIdx.x) >> 5;
    int lane = threadIdx.x & 31;
    if (w >= N_NODES) return;
    float4 r = row_mean_h(count, bucket, invdeg, x2, w, lane);
    long o = (long)w * VEC + lane;
    float4 v0 = (w < N_USERS) ? __ldcs(&ue[o]) : __ldcs(&ie[o - (long)N_USERS * VEC]);
    float4 v1 = h4_to_f4(__ldcs(&x1[o]));
    float4 v2 = h4_to_f4(__ldg(&x2[o]));      // hot in L2 (gather table)
    float4 ov;
    ov.x = 0.25f * (v0.x + v1.x + v2.x + r.x);
    ov.y = 0.25f * (v0.y + v1.y + v2.y + r.y);
    ov.z = 0.25f * (v0.z + v1.z + v2.z + r.z);
    ov.w = 0.25f * (v0.w + v1.w + v2.w + r.w);
    __stcs(&out[o], ov);
}

extern "C" void kernel_launch(void* const* d_in, const int* in_sizes, int n_in,
                              void* d_out, int out_size) {
    const float* ue = (const float*)d_in[0];           // [N_USERS, 128]
    const float* ie = (const float*)d_in[1];           // [N_ITEMS, 128]
    const int*   ei = (const int*)d_in[2];             // [2, N_EDGES] int32
    const int* src = ei;
    const int* dst = ei + N_EDGES;
    float* out = (float*)d_out;                        // [N_NODES, 128] fp32

    uint2 *x0h, *x1, *x2;
    float *invdeg;
    int *count, *bucket, *sdst, *ssrc, *scnt;
    cudaGetSymbolAddress((void**)&x0h, g_x0h);
    cudaGetSymbolAddress((void**)&x1, g_x1);
    cudaGetSymbolAddress((void**)&x2, g_x2);
    cudaGetSymbolAddress((void**)&invdeg, g_invdeg);
    cudaGetSymbolAddress((void**)&count, g_count);
    cudaGetSymbolAddress((void**)&bucket, g_bucket);
    cudaGetSymbolAddress((void**)&sdst, g_spill_dst);
    cudaGetSymbolAddress((void**)&ssrc, g_spill_src);
    cudaGetSymbolAddress((void**)&scnt, g_spill_count);

    const int BT = 256;
    const long nvec = (long)N_NODES * VEC;             // 5,120,000

    // ---- build: convert + direct bucket binning (no histogram/scan) ----
    cudaMemsetAsync(count, 0, N_NODES * sizeof(int));
    cudaMemsetAsync(scnt, 0, sizeof(int));
    convert_kernel<<<(int)((nvec + BT - 1) / BT), BT>>>(
        (const float4*)ue, (const float4*)ie, x0h);
    permute_kernel<<<(N_EDGES / 2 + BT - 1) / BT, BT>>>(
        (const int2*)src, (const int2*)dst, count, bucket, sdst, ssrc, scnt);
    invdeg_kernel<<<(N_NODES + BT - 1) / BT, BT>>>(count, invdeg);

    // ---- 3 propagation layers (warp per node) + sequential spill fixups ----
    const int blocks = (N_NODES * 32 + BT - 1) / BT;
    layer_kernel<<<blocks, BT>>>(count, bucket, invdeg, x0h, x1);
    fixup_h_kernel<<<1, 32>>>(sdst, ssrc, scnt, invdeg, x0h, x1);
    layer_kernel<<<blocks, BT>>>(count, bucket, invdeg, x1, x2);
    fixup_h_kernel<<<1, 32>>>(sdst, ssrc, scnt, invdeg, x1, x2);
    layer3_kernel<<<blocks, BT>>>(count, bucket, invdeg,
                                  (const float4*)ue, (const float4*)ie,
                                  x1, x2, (float4*)out);
    fixup_f_kernel<<<1, 32>>>(sdst, ssrc, scnt, invdeg, x2, (float4*)out);
}

// round 16
// speedup vs baseline: 1.0362x; 1.0362x over previous
#include <cuda_runtime.h>
#include <cuda_fp16.h>
#include <cstdint>

#define N_USERS 100000
#define N_ITEMS 60000
#define N_NODES (N_USERS + N_ITEMS)
#define EMB_DIM 128
#define VEC (EMB_DIM / 4)        // 32 chunks/row: float4 (fp32) or uint2 (fp16x4)
#define N_EDGES 1500000
// csr with per-node padding to 4-int alignment: worst case +3 per node
#define CSR_CAP (N_EDGES + 4 * N_NODES)

static_assert((N_EDGES & 1) == 0, "permute int2 path requires even N_EDGES");

// Scratch (__device__ globals per allocation-free rule)
__device__ uint2 g_x0h[(size_t)N_NODES * VEC];
__device__ uint2 g_x1[(size_t)N_NODES * VEC];
__device__ uint2 g_x2[(size_t)N_NODES * VEC];
__device__ float g_invdeg[N_NODES];
__device__ int   g_deg[N_NODES];
__device__ int   g_rowptr[N_NODES];
__device__ int   g_cursor[N_NODES];
__device__ int   g_csr[CSR_CAP];        // ~8.6 MB, segments 16B-aligned
__device__ int   g_counter[1];

// ---------------------------------------------------------------------------
__device__ __forceinline__ __half2 h2(uint32_t b) {
    return *reinterpret_cast<__half2*>(&b);
}
__device__ __forceinline__ float4 h4_to_f4(uint2 u) {
    float2 lo = __half22float2(h2(u.x));
    float2 hi = __half22float2(h2(u.y));
    float4 r; r.x = lo.x; r.y = lo.y; r.z = hi.x; r.w = hi.y;
    return r;
}
__device__ __forceinline__ uint2 f4_to_h4(float4 v) {
    __half2 lo = __floats2half2_rn(v.x, v.y);
    __half2 hi = __floats2half2_rn(v.z, v.w);
    uint2 u;
    u.x = *reinterpret_cast<uint32_t*>(&lo);
    u.y = *reinterpret_cast<uint32_t*>(&hi);
    return u;
}

// 1) fused: convert concat(ue,ie) fp32->fp16 table  +  dst degree histogram
__global__ void convhist_kernel(const float4* __restrict__ ue,
                                const float4* __restrict__ ie,
                                uint2* __restrict__ x0h,
                                const int* __restrict__ dst,
                                int* __restrict__ deg) {
    long i = (long)blockIdx.x * blockDim.x + threadIdx.x;
    const long total = (long)N_NODES * VEC;        // 5,120,000
    if (i < total) {
        const long user_lim = (long)N_USERS * VEC;
        float4 v = (i < user_lim) ? __ldcs(&ue[i]) : __ldcs(&ie[i - user_lim]);
        __stcs(&x0h[i], f4_to_h4(v));
    }
    if (i < N_EDGES) atomicAdd(&deg[dst[(int)i]], 1);
}

// 2) segment assignment via global cursor; segments rounded up to 4 ints so
//    every row start is 16B-aligned (enables int4 index loads). + invdeg.
__global__ void assign_kernel(const int* __restrict__ deg,
                              int* __restrict__ rowptr,
                              int* __restrict__ cursor,
                              float* __restrict__ invdeg,
                              int* __restrict__ counter) {
    int v = blockIdx.x * blockDim.x + threadIdx.x;
    if (v >= N_NODES) return;
    int d = deg[v];
    int pad = (d + 3) & ~3;
    int beg = (d > 0) ? atomicAdd(counter, pad) : 0;
    rowptr[v] = beg;
    cursor[v] = beg;
    invdeg[v] = (d > 0) ? (1.0f / (float)d) : 0.0f;
}

// 3) bin edges by dst; two edges per thread (int2 index loads)
__global__ void permute_kernel(const int2* __restrict__ src2,
                               const int2* __restrict__ dst2,
                               int* __restrict__ cursor,
                               int* __restrict__ csr) {
    int t = blockIdx.x * blockDim.x + threadIdx.x;
    if (t >= N_EDGES / 2) return;
    int2 s = __ldg(&src2[t]);
    int2 d = __ldg(&dst2[t]);
    int p0 = atomicAdd(&cursor[d.x], 1);
    csr[p0] = s.x;
    int p1 = atomicAdd(&cursor[d.y], 1);
    csr[p1] = s.y;
}

// ---------------------------------------------------------------------------
// Warp-per-node mean over an fp16 table. Row segment start is 16B-aligned, so
// index loads are uniform int4 (2 LDG.128 per 8-edge iter). Depth-3 HADD2
// tree, one convert per half2 chunk, fp32 cross-group accumulation.
__device__ __forceinline__ float4 row_mean_h(const int* __restrict__ rowptr,
                                             const int* __restrict__ deg,
                                             const int* __restrict__ csr,
                                             const float* __restrict__ invdeg,
                                             const uint2* __restrict__ xin,
                                             int w, int lane) {
    int beg = __ldg(&rowptr[w]);      // multiple of 4
    int n = __ldg(&deg[w]);
    const int4* b4 = reinterpret_cast<const int4*>(csr + beg);
    float2 aLo = {0.f, 0.f}, aHi = {0.f, 0.f};
    int j = 0;
    for (; j + 8 <= n; j += 8) {
        int4 A = __ldg(&b4[j >> 2]);
        int4 B = __ldg(&b4[(j >> 2) + 1]);
        uint2 u0 = __ldg(&xin[(long)A.x * VEC + lane]);
        uint2 u1 = __ldg(&xin[(long)A.y * VEC + lane]);
        uint2 u2 = __ldg(&xin[(long)A.z * VEC + lane]);
        uint2 u3 = __ldg(&xin[(long)A.w * VEC + lane]);
        uint2 u4 = __ldg(&xin[(long)B.x * VEC + lane]);
        uint2 u5 = __ldg(&xin[(long)B.y * VEC + lane]);
        uint2 u6 = __ldg(&xin[(long)B.z * VEC + lane]);
        uint2 u7 = __ldg(&xin[(long)B.w * VEC + lane]);
        __half2 tL = __hadd2(__hadd2(__hadd2(h2(u0.x), h2(u1.x)),
                                     __hadd2(h2(u2.x), h2(u3.x))),
                             __hadd2(__hadd2(h2(u4.x), h2(u5.x)),
                                     __hadd2(h2(u6.x), h2(u7.x))));
        __half2 tH = __hadd2(__hadd2(__hadd2(h2(u0.y), h2(u1.y)),
                                     __hadd2(h2(u2.y), h2(u3.y))),
                             __hadd2(__hadd2(h2(u4.y), h2(u5.y)),
                                     __hadd2(h2(u6.y), h2(u7.y))));
        float2 f;
        f = __half22float2(tL); aLo.x += f.x; aLo.y += f.y;
        f = __half22float2(tH); aHi.x += f.x; aHi.y += f.y;
    }
    for (; j + 4 <= n; j += 4) {
        int4 A = __ldg(&b4[j >> 2]);
        uint2 u0 = __ldg(&xin[(long)A.x * VEC + lane]);
        uint2 u1 = __ldg(&xin[(long)A.y * VEC + lane]);
        uint2 u2 = __ldg(&xin[(long)A.z * VEC + lane]);
        uint2 u3 = __ldg(&xin[(long)A.w * VEC + lane]);
        __half2 tL = __hadd2(__hadd2(h2(u0.x), h2(u1.x)),
                             __hadd2(h2(u2.x), h2(u3.x)));
        __half2 tH = __hadd2(__hadd2(h2(u0.y), h2(u1.y)),
                             __hadd2(h2(u2.y), h2(u3.y)));
        float2 f;
        f = __half22float2(tL); aLo.x += f.x; aLo.y += f.y;
        f = __half22float2(tH); aHi.x += f.x; aHi.y += f.y;
    }
    const int* bs = csr + beg;
    for (; j < n; ++j) {                 // <=3 remainders in fp32
        int s = __ldg(&bs[j]);
        float4 v = h4_to_f4(__ldg(&xin[(long)s * VEC + lane]));
        aLo.x += v.x; aLo.y += v.y; aHi.x += v.z; aHi.y += v.w;
    }
    float sc = __ldg(&invdeg[w]);
    float4 r;
    r.x = aLo.x * sc; r.y = aLo.y * sc;
    r.z = aHi.x * sc; r.w = aHi.y * sc;
    return r;
}

// Layers 1 & 2: xout (fp16) = A~ @ xin (fp16)
__global__ void __launch_bounds__(256)
layer_kernel(const int* __restrict__ rowptr, const int* __restrict__ deg,
             const int* __restrict__ csr, const float* __restrict__ invdeg,
             const uint2* __restrict__ xin, uint2* __restrict__ xout) {
    int w = (blockIdx.x * blockDim.x + threadIdx.x) >> 5;
    int lane = threadIdx.x & 31;
    if (w >= N_NODES) return;
    float4 r = row_mean_h(rowptr, deg, csr, invdeg, xin, w, lane);
    xout[(long)w * VEC + lane] = f4_to_h4(r);   // next gather table: keep in L2
}

// Layer 3 fused finale: r = A~ @ x2 (regs only); out = 0.25*(x0_fp32+x1+x2+r)
__global__ void __launch_bounds__(256)
layer3_kernel(const int* __restrict__ rowptr, const int* __restrict__ deg,
              const int* __restrict__ csr, const float* __restrict__ invdeg,
              const float4* __restrict__ ue, const float4* __restrict__ ie,
              const uint2* __restrict__ x1, const uint2* __restrict__ x2,
              float4* __restrict__ out) {
    int w = (blockIdx.x * blockDim.x + threadIdx.x) >> 5;
    int lane = threadIdx.x & 31;
    if (w >= N_NODES) return;
    float4 r = row_mean_h(rowptr, deg, csr, invdeg, x2, w, lane);
    long o = (long)w * VEC + lane;
    float4 v0 = (w < N_USERS) ? __ldcs(&ue[o]) : __ldcs(&ie[o - (long)N_USERS * VEC]);
    float4 v1 = h4_to_f4(__ldcs(&x1[o]));
    float4 v2 = h4_to_f4(__ldg(&x2[o]));      // hot in L2 (gather table)
    float4 ov;
    ov.x = 0.25f * (v0.x + v1.x + v2.x + r.x);
    ov.y = 0.25f * (v0.y + v1.y + v2.y + r.y);
    ov.z = 0.25f * (v0.z + v1.z + v2.z + r.z);
    ov.w = 0.25f * (v0.w + v1.w + v2.w + r.w);
    __stcs(&out[o], ov);
}

extern "C" void kernel_launch(void* const* d_in, const int* in_sizes, int n_in,
                              void* d_out, int out_size) {
    const float* ue = (const float*)d_in[0];           // [N_USERS, 128]
    const float* ie = (const float*)d_in[1];           // [N_ITEMS, 128]
    const int*   ei = (const int*)d_in[2];             // [2, N_EDGES] int32
    const int* src = ei;
    const int* dst = ei + N_EDGES;
    float* out = (float*)d_out;                        // [N_NODES, 128] fp32

    uint2 *x0h, *x1, *x2;
    float *invdeg;
    int *deg, *rowptr, *cursor, *csr, *counter;
    cudaGetSymbolAddress((void**)&x0h, g_x0h);
    cudaGetSymbolAddress((void**)&x1, g_x1);
    cudaGetSymbolAddress((void**)&x2, g_x2);
    cudaGetSymbolAddress((void**)&invdeg, g_invdeg);
    cudaGetSymbolAddress((void**)&deg, g_deg);
    cudaGetSymbolAddress((void**)&rowptr, g_rowptr);
    cudaGetSymbolAddress((void**)&cursor, g_cursor);
    cudaGetSymbolAddress((void**)&csr, g_csr);
    cudaGetSymbolAddress((void**)&counter, g_counter);

    const int BT = 256;
    const long nvec = (long)N_NODES * VEC;             // 5,120,000

    // ---- CSR build (scan-free, 16B-aligned segments) + fp16 conversion ----
    cudaMemsetAsync(deg, 0, N_NODES * sizeof(int));
    cudaMemsetAsync(counter, 0, sizeof(int));
    convhist_kernel<<<(int)((nvec + BT - 1) / BT), BT>>>(
        (const float4*)ue, (const float4*)ie, x0h, dst, deg);
    assign_kernel<<<(N_NODES + BT - 1) / BT, BT>>>(deg, rowptr, cursor,
                                                   invdeg, counter);
    permute_kernel<<<(N_EDGES / 2 + BT - 1) / BT, BT>>>(
        (const int2*)src, (const int2*)dst, cursor, csr);

    // ---- 3 propagation layers (warp per node); layer1 = 4th launch -> ncu ----
    const int blocks = (N_NODES * 32 + BT - 1) / BT;
    layer_kernel<<<blocks, BT>>>(rowptr, deg, csr, invdeg, x0h, x1);
    layer_kernel<<<blocks, BT>>>(rowptr, deg, csr, invdeg, x1, x2);
    layer3_kernel<<<blocks, BT>>>(rowptr, deg, csr, invdeg,
                                  (const float4*)ue, (const float4*)ie,
                                  x1, x2, (float4*)out);
}

// round 17
// speedup vs baseline: 1.0769x; 1.0393x over previous
#include <cuda_runtime.h>
#include <cuda_fp16.h>
#include <cstdint>

#define N_USERS 100000
#define N_ITEMS 60000
#define N_NODES (N_USERS + N_ITEMS)
#define EMB_DIM 128
#define VEC (EMB_DIM / 4)        // 32 chunks/row: float4 (fp32) or uint2 (fp16x4)
#define N_EDGES 1500000
#define ROWS (N_NODES + 1)       // +1 zero row for padding gathers
#define ZROW N_NODES             // dummy node index
#define CSR_CAP (N_EDGES + 8 * N_NODES)   // pad-to-8 worst case

static_assert((N_EDGES & 1) == 0, "permute int2 path requires even N_EDGES");

// Scratch (__device__ globals per allocation-free rule)
__device__ uint2 g_x0h[(size_t)ROWS * VEC];
__device__ uint2 g_x1[(size_t)ROWS * VEC];
__device__ uint2 g_x2[(size_t)ROWS * VEC];
__device__ float g_invdeg[N_NODES];
__device__ int   g_deg[N_NODES];
__device__ int2  g_meta[N_NODES];        // {segment begin, true degree}
__device__ int   g_cursor[N_NODES];
__device__ int   g_csr[CSR_CAP];         // ~11 MB, rows padded to 8 with ZROW
__device__ int   g_counter[1];

// ---------------------------------------------------------------------------
__device__ __forceinline__ __half2 h2(uint32_t b) {
    return *reinterpret_cast<__half2*>(&b);
}
__device__ __forceinline__ float4 h4_to_f4(uint2 u) {
    float2 lo = __half22float2(h2(u.x));
    float2 hi = __half22float2(h2(u.y));
    float4 r; r.x = lo.x; r.y = lo.y; r.z = hi.x; r.w = hi.y;
    return r;
}
__device__ __forceinline__ uint2 f4_to_h4(float4 v) {
    __half2 lo = __floats2half2_rn(v.x, v.y);
    __half2 hi = __floats2half2_rn(v.z, v.w);
    uint2 u;
    u.x = *reinterpret_cast<uint32_t*>(&lo);
    u.y = *reinterpret_cast<uint32_t*>(&hi);
    return u;
}

// 1) fused: convert concat(ue,ie) fp32->fp16 table  +  dst degree histogram
__global__ void convhist_kernel(const float4* __restrict__ ue,
                                const float4* __restrict__ ie,
                                uint2* __restrict__ x0h,
                                const int* __restrict__ dst,
                                int* __restrict__ deg) {
    long i = (long)blockIdx.x * blockDim.x + threadIdx.x;
    const long total = (long)N_NODES * VEC;        // 5,120,000
    if (i < total) {
        const long user_lim = (long)N_USERS * VEC;
        float4 v = (i < user_lim) ? __ldcs(&ue[i]) : __ldcs(&ie[i - user_lim]);
        __stcs(&x0h[i], f4_to_h4(v));
    }
    if (i < N_EDGES) atomicAdd(&deg[dst[(int)i]], 1);
}

// 2) segment assignment (pad-to-8) via global cursor + invdeg + pad fill
__global__ void assign_kernel(const int* __restrict__ deg,
                              int2* __restrict__ meta,
                              int* __restrict__ cursor,
                              float* __restrict__ invdeg,
                              int* __restrict__ counter,
                              int* __restrict__ csr) {
    int v = blockIdx.x * blockDim.x + threadIdx.x;
    if (v >= N_NODES) return;
    int d = deg[v];
    int p8 = (d + 7) & ~7;
    int beg = (d > 0) ? atomicAdd(counter, p8) : 0;
    int2 m; m.x = beg; m.y = d;
    meta[v] = m;
    cursor[v] = beg;
    invdeg[v] = (d > 0) ? (1.0f / (float)d) : 0.0f;
    for (int k = d; k < p8; ++k) csr[beg + k] = ZROW;   // zero-row padding
}

// 3) bin edges by dst; two edges per thread (int2 index loads)
__global__ void permute_kernel(const int2* __restrict__ src2,
                               const int2* __restrict__ dst2,
                               int* __restrict__ cursor,
                               int* __restrict__ csr) {
    int t = blockIdx.x * blockDim.x + threadIdx.x;
    if (t >= N_EDGES / 2) return;
    int2 s = __ldg(&src2[t]);
    int2 d = __ldg(&dst2[t]);
    int p0 = atomicAdd(&cursor[d.x], 1);
    csr[p0] = s.x;
    int p1 = atomicAdd(&cursor[d.y], 1);
    csr[p1] = s.y;
}

// ---------------------------------------------------------------------------
// Warp-per-node mean over an fp16 table. Segments padded to 8 with the zero
// row, so the 8-edge mainloop is the ONLY loop: no 4-wide section, no scalar
// remainder, no divergent section branching. Depth-3 HADD2 tree (zeros are
// free), one convert per half2 chunk, fp32 cross-group accumulation.
__device__ __forceinline__ float4 row_mean_h(const int2* __restrict__ meta,
                                             const int* __restrict__ csr,
                                             const float* __restrict__ invdeg,
                                             const uint2* __restrict__ xin,
                                             int w, int lane) {
    int2 m = __ldg(&meta[w]);
    const int* bs = csr + m.x;
    int n = (m.y + 7) & ~7;
    float2 aLo = {0.f, 0.f}, aHi = {0.f, 0.f};
    for (int j = 0; j < n; j += 8) {
        int s0 = bs[j],   s1 = bs[j+1], s2 = bs[j+2], s3 = bs[j+3];
        int s4 = bs[j+4], s5 = bs[j+5], s6 = bs[j+6], s7 = bs[j+7];
        uint2 u0 = __ldg(&xin[(long)s0 * VEC + lane]);
        uint2 u1 = __ldg(&xin[(long)s1 * VEC + lane]);
        uint2 u2 = __ldg(&xin[(long)s2 * VEC + lane]);
        uint2 u3 = __ldg(&xin[(long)s3 * VEC + lane]);
        uint2 u4 = __ldg(&xin[(long)s4 * VEC + lane]);
        uint2 u5 = __ldg(&xin[(long)s5 * VEC + lane]);
        uint2 u6 = __ldg(&xin[(long)s6 * VEC + lane]);
        uint2 u7 = __ldg(&xin[(long)s7 * VEC + lane]);
        __half2 tL = __hadd2(__hadd2(__hadd2(h2(u0.x), h2(u1.x)),
                                     __hadd2(h2(u2.x), h2(u3.x))),
                             __hadd2(__hadd2(h2(u4.x), h2(u5.x)),
                                     __hadd2(h2(u6.x), h2(u7.x))));
        __half2 tH = __hadd2(__hadd2(__hadd2(h2(u0.y), h2(u1.y)),
                                     __hadd2(h2(u2.y), h2(u3.y))),
                             __hadd2(__hadd2(h2(u4.y), h2(u5.y)),
                                     __hadd2(h2(u6.y), h2(u7.y))));
        float2 f;
        f = __half22float2(tL); aLo.x += f.x; aLo.y += f.y;
        f = __half22float2(tH); aHi.x += f.x; aHi.y += f.y;
    }
    float sc = __ldg(&invdeg[w]);
    float4 r;
    r.x = aLo.x * sc; r.y = aLo.y * sc;
    r.z = aHi.x * sc; r.w = aHi.y * sc;
    return r;
}

// Layers 1 & 2: xout (fp16) = A~ @ xin (fp16)
__global__ void __launch_bounds__(256)
layer_kernel(const int2* __restrict__ meta, const int* __restrict__ csr,
             const float* __restrict__ invdeg,
             const uint2* __restrict__ xin, uint2* __restrict__ xout) {
    int w = (blockIdx.x * blockDim.x + threadIdx.x) >> 5;
    int lane = threadIdx.x & 31;
    if (w >= N_NODES) return;
    float4 r = row_mean_h(meta, csr, invdeg, xin, w, lane);
    xout[(long)w * VEC + lane] = f4_to_h4(r);   // next gather table: keep in L2
}

// Layer 3 fused finale: r = A~ @ x2 (regs only); out = 0.25*(x0h+x1+x2+r)
__global__ void __launch_bounds__(256)
layer3_kernel(const int2* __restrict__ meta, const int* __restrict__ csr,
              const float* __restrict__ invdeg,
              const uint2* __restrict__ x0h,
              const uint2* __restrict__ x1, const uint2* __restrict__ x2,
              float4* __restrict__ out) {
    int w = (blockIdx.x * blockDim.x + threadIdx.x) >> 5;
    int lane = threadIdx.x & 31;
    if (w >= N_NODES) return;
    float4 r = row_mean_h(meta, csr, invdeg, x2, w, lane);
    long o = (long)w * VEC + lane;
    float4 v0 = h4_to_f4(__ldcs(&x0h[o]));
    float4 v1 = h4_to_f4(__ldcs(&x1[o]));
    float4 v2 = h4_to_f4(__ldg(&x2[o]));      // hot in L2 (gather table)
    float4 ov;
    ov.x = 0.25f * (v0.x + v1.x + v2.x + r.x);
    ov.y = 0.25f * (v0.y + v1.y + v2.y + r.y);
    ov.z = 0.25f * (v0.z + v1.z + v2.z + r.z);
    ov.w = 0.25f * (v0.w + v1.w + v2.w + r.w);
    __stcs(&out[o], ov);
}

extern "C" void kernel_launch(void* const* d_in, const int* in_sizes, int n_in,
                              void* d_out, int out_size) {
    const float* ue = (const float*)d_in[0];           // [N_USERS, 128]
    const float* ie = (const float*)d_in[1];           // [N_ITEMS, 128]
    const int*   ei = (const int*)d_in[2];             // [2, N_EDGES] int32
    const int* src = ei;
    const int* dst = ei + N_EDGES;
    float* out = (float*)d_out;                        // [N_NODES, 128] fp32

    uint2 *x0h, *x1, *x2;
    float *invdeg;
    int *deg, *cursor, *csr, *counter;
    int2 *meta;
    cudaGetSymbolAddress((void**)&x0h, g_x0h);
    cudaGetSymbolAddress((void**)&x1, g_x1);
    cudaGetSymbolAddress((void**)&x2, g_x2);
    cudaGetSymbolAddress((void**)&invdeg, g_invdeg);
    cudaGetSymbolAddress((void**)&deg, g_deg);
    cudaGetSymbolAddress((void**)&meta, g_meta);
    cudaGetSymbolAddress((void**)&cursor, g_cursor);
    cudaGetSymbolAddress((void**)&csr, g_csr);
    cudaGetSymbolAddress((void**)&counter, g_counter);

    const int BT = 256;
    const long nvec = (long)N_NODES * VEC;             // 5,120,000
    const size_t rowbytes = (size_t)VEC * sizeof(uint2);   // 256 B

    // ---- zero rows (gather target for padded edges) + build scratch ----
    cudaMemsetAsync(deg, 0, N_NODES * sizeof(int));
    cudaMemsetAsync(counter, 0, sizeof(int));
    cudaMemsetAsync(x0h + (size_t)ZROW * VEC, 0, rowbytes);
    cudaMemsetAsync(x1 + (size_t)ZROW * VEC, 0, rowbytes);
    cudaMemsetAsync(x2 + (size_t)ZROW * VEC, 0, rowbytes);

    // ---- CSR build (scan-free, pad-to-8 segments) + fp16 conversion ----
    convhist_kernel<<<(int)((nvec + BT - 1) / BT), BT>>>(
        (const float4*)ue, (const float4*)ie, x0h, dst, deg);
    assign_kernel<<<(N_NODES + BT - 1) / BT, BT>>>(deg, meta, cursor,
                                                   invdeg, counter, csr);
    permute_kernel<<<(N_EDGES / 2 + BT - 1) / BT, BT>>>(
        (const int2*)src, (const int2*)dst, cursor, csr);

    // ---- 3 propagation layers (warp per node); layer1 = 4th launch -> ncu ----
    const int blocks = (N_NODES * 32 + BT - 1) / BT;
    layer_kernel<<<blocks, BT>>>(meta, csr, invdeg, x0h, x1);
    layer_kernel<<<blocks, BT>>>(meta, csr, invdeg, x1, x2);
    layer3_kernel<<<blocks, BT>>>(meta, csr, invdeg, x0h, x1, x2,
                                  (float4*)out);
}